// round 1
// baseline (speedup 1.0000x reference)
#include <cuda_runtime.h>

// Problem constants
#define SEQ   2048
#define DMODEL 2048
#define NHEAD 8
#define HD    256
#define BATCH 2
#define BH    (BATCH * NHEAD)

// Scratch (alloc-guard compliant: __device__ globals)
__device__ float g_q[(size_t)BATCH * SEQ * DMODEL];   // [b*S+s][h*HD+d], RoPE'd in place
__device__ float g_k[(size_t)BATCH * SEQ * HD];       // [b*S+s][d], RoPE'd in place
__device__ float g_v[(size_t)BATCH * SEQ * HD];       // [b*S+s][d]
__device__ float g_attn[(size_t)BATCH * SEQ * DMODEL];// [b*S+s][h*HD+d]

// ---------------- SGEMM 128x128x8, 256 threads, 8x8 per-thread ----------------
#define BM 128
#define BN 128
#define BKK 8
#define TM 8
#define TN 8

// C[M,N] = alpha * A[M,K](lda) @ B[N,K](ldb)^T   (both K-major: "NT")
__device__ __forceinline__ void gemm_nt_body(
    const float* __restrict__ A, int lda,
    const float* __restrict__ B, int ldb,
    float* __restrict__ C, int ldc,
    int K, float alpha)
{
    __shared__ float As[BKK][BM];
    __shared__ float Bs[BKK][BN];
    const int tid = threadIdx.x;
    const int tx = tid & 15;
    const int ty = tid >> 4;
    const int rowBase = blockIdx.y * BM;
    const int colBase = blockIdx.x * BN;
    const int loadRow = tid >> 1;          // 0..127
    const int loadCol = (tid & 1) * 4;     // 0 or 4

    float acc[TM][TN];
#pragma unroll
    for (int i = 0; i < TM; i++)
#pragma unroll
        for (int j = 0; j < TN; j++) acc[i][j] = 0.f;

    for (int k0 = 0; k0 < K; k0 += BKK) {
        float4 a4 = *(const float4*)(A + (size_t)(rowBase + loadRow) * lda + k0 + loadCol);
        float4 b4 = *(const float4*)(B + (size_t)(colBase + loadRow) * ldb + k0 + loadCol);
        As[loadCol + 0][loadRow] = a4.x;
        As[loadCol + 1][loadRow] = a4.y;
        As[loadCol + 2][loadRow] = a4.z;
        As[loadCol + 3][loadRow] = a4.w;
        Bs[loadCol + 0][loadRow] = b4.x;
        Bs[loadCol + 1][loadRow] = b4.y;
        Bs[loadCol + 2][loadRow] = b4.z;
        Bs[loadCol + 3][loadRow] = b4.w;
        __syncthreads();
#pragma unroll
        for (int kk = 0; kk < BKK; kk++) {
            float4 a0 = *(const float4*)&As[kk][ty * TM];
            float4 a1 = *(const float4*)&As[kk][ty * TM + 4];
            float4 b0 = *(const float4*)&Bs[kk][tx * TN];
            float4 b1 = *(const float4*)&Bs[kk][tx * TN + 4];
            float ar[TM] = {a0.x, a0.y, a0.z, a0.w, a1.x, a1.y, a1.z, a1.w};
            float br[TN] = {b0.x, b0.y, b0.z, b0.w, b1.x, b1.y, b1.z, b1.w};
#pragma unroll
            for (int i = 0; i < TM; i++)
#pragma unroll
                for (int j = 0; j < TN; j++) acc[i][j] += ar[i] * br[j];
        }
        __syncthreads();
    }
#pragma unroll
    for (int i = 0; i < TM; i++) {
        float* crow = C + (size_t)(rowBase + ty * TM + i) * ldc + colBase + tx * TN;
        float4 c0, c1;
        c0.x = alpha * acc[i][0]; c0.y = alpha * acc[i][1];
        c0.z = alpha * acc[i][2]; c0.w = alpha * acc[i][3];
        c1.x = alpha * acc[i][4]; c1.y = alpha * acc[i][5];
        c1.z = alpha * acc[i][6]; c1.w = alpha * acc[i][7];
        *(float4*)(crow)     = c0;
        *(float4*)(crow + 4) = c1;
    }
}

// C[M,N] = A[M,K](lda) @ B[K,N](ldb)   ("NN", B row-major K x N)
__device__ __forceinline__ void gemm_nn_body(
    const float* __restrict__ A, int lda,
    const float* __restrict__ B, int ldb,
    float* __restrict__ C, int ldc,
    int K)
{
    __shared__ float As[BKK][BM];
    __shared__ float Bs[BKK][BN];
    const int tid = threadIdx.x;
    const int tx = tid & 15;
    const int ty = tid >> 4;
    const int rowBase = blockIdx.y * BM;
    const int colBase = blockIdx.x * BN;
    const int aRow = tid >> 1;
    const int aCol = (tid & 1) * 4;
    const int bKRow = tid >> 5;            // 0..7
    const int bNCol = (tid & 31) * 4;      // 0..124

    float acc[TM][TN];
#pragma unroll
    for (int i = 0; i < TM; i++)
#pragma unroll
        for (int j = 0; j < TN; j++) acc[i][j] = 0.f;

    for (int k0 = 0; k0 < K; k0 += BKK) {
        float4 a4 = *(const float4*)(A + (size_t)(rowBase + aRow) * lda + k0 + aCol);
        float4 b4 = *(const float4*)(B + (size_t)(k0 + bKRow) * ldb + colBase + bNCol);
        As[aCol + 0][aRow] = a4.x;
        As[aCol + 1][aRow] = a4.y;
        As[aCol + 2][aRow] = a4.z;
        As[aCol + 3][aRow] = a4.w;
        *(float4*)&Bs[bKRow][bNCol] = b4;
        __syncthreads();
#pragma unroll
        for (int kk = 0; kk < BKK; kk++) {
            float4 a0 = *(const float4*)&As[kk][ty * TM];
            float4 a1 = *(const float4*)&As[kk][ty * TM + 4];
            float4 b0 = *(const float4*)&Bs[kk][tx * TN];
            float4 b1 = *(const float4*)&Bs[kk][tx * TN + 4];
            float ar[TM] = {a0.x, a0.y, a0.z, a0.w, a1.x, a1.y, a1.z, a1.w};
            float br[TN] = {b0.x, b0.y, b0.z, b0.w, b1.x, b1.y, b1.z, b1.w};
#pragma unroll
            for (int i = 0; i < TM; i++)
#pragma unroll
                for (int j = 0; j < TN; j++) acc[i][j] += ar[i] * br[j];
        }
        __syncthreads();
    }
#pragma unroll
    for (int i = 0; i < TM; i++) {
        float* crow = C + (size_t)(rowBase + ty * TM + i) * ldc + colBase + tx * TN;
        float4 c0 = {acc[i][0], acc[i][1], acc[i][2], acc[i][3]};
        float4 c1 = {acc[i][4], acc[i][5], acc[i][6], acc[i][7]};
        *(float4*)(crow)     = c0;
        *(float4*)(crow + 4) = c1;
    }
}

// ---------------- kernels ----------------

__global__ __launch_bounds__(256) void k_proj_q(const float* __restrict__ hidden,
                                                const float* __restrict__ Wq) {
    gemm_nt_body(hidden, DMODEL, Wq, DMODEL, g_q, DMODEL, DMODEL, 1.0f);
}
__global__ __launch_bounds__(256) void k_proj_k(const float* __restrict__ hidden,
                                                const float* __restrict__ Wk) {
    gemm_nt_body(hidden, DMODEL, Wk, DMODEL, g_k, HD, DMODEL, 1.0f);
}
__global__ __launch_bounds__(256) void k_proj_v(const float* __restrict__ hidden,
                                                const float* __restrict__ Wv) {
    gemm_nt_body(hidden, DMODEL, Wv, DMODEL, g_v, HD, DMODEL, 1.0f);
}
__global__ __launch_bounds__(256) void k_final(const float* __restrict__ Wo,
                                               float* __restrict__ out) {
    gemm_nt_body(g_attn, DMODEL, Wo, DMODEL, out, DMODEL, DMODEL, 1.0f);
}

// RoPE in-place on g_q (8 head slots) and g_k (slot 8). One thread per (row, slot, pair j).
__global__ __launch_bounds__(256) void k_rope(const int* __restrict__ pos_ids) {
    int idx = blockIdx.x * blockDim.x + threadIdx.x;
    const int total = BATCH * SEQ * (NHEAD + 1) * 128;
    if (idx >= total) return;
    int j    = idx & 127;
    int rest = idx >> 7;
    int slot = rest % (NHEAD + 1);
    int row  = rest / (NHEAD + 1);        // b*S + s
    float pos = (float)pos_ids[row];
    // inv_freq = 10000^(-2j/256) = 2^(-(2j/256)*log2(10000))
    float f = exp2f(-((float)(2 * j) * (1.0f / (float)HD)) * 13.287712379549449f);
    float ang = pos * f;
    float sv, cv;
    sincosf(ang, &sv, &cv);
    float* p1;
    if (slot < NHEAD) p1 = &g_q[(size_t)row * DMODEL + slot * HD + j];
    else              p1 = &g_k[(size_t)row * HD + j];
    float* p2 = p1 + 128;
    float x1 = *p1, x2 = *p2;
    *p1 = x1 * cv - x2 * sv;
    *p2 = x2 * cv + x1 * sv;
}

// scores[bh] = (Q_bh @ K_b^T) / 16, only lower-triangular tiles (causal block-skip)
__global__ __launch_bounds__(256) void k_scores(float* __restrict__ weights) {
    if (blockIdx.x > blockIdx.y) return;   // fully-masked tile
    const int bh = blockIdx.z;
    const int b  = bh / NHEAD;
    const int h  = bh % NHEAD;
    const float* A = g_q + (size_t)b * SEQ * DMODEL + h * HD;  // lda = DMODEL
    const float* B = g_k + (size_t)b * SEQ * HD;               // ldb = HD
    float* C = weights + (size_t)bh * SEQ * SEQ;               // ldc = SEQ
    gemm_nt_body(A, DMODEL, B, HD, C, SEQ, HD, 0.0625f);
}

// row-wise causal softmax in-place on weights; zero masked tail
__global__ __launch_bounds__(256) void k_softmax(float* __restrict__ w) {
    const int row = blockIdx.x;                 // bh*S + q
    const int q = row & (SEQ - 1);
    float* p = w + (size_t)row * SEQ;
    const int len = q + 1;
    const int tid = threadIdx.x;
    __shared__ float red[256];

    float vals[SEQ / 256];
    int cnt = 0;
    float m = -3.4e38f;
    for (int i = tid; i < len; i += 256) {
        float x = p[i];
        vals[cnt++] = x;
        m = fmaxf(m, x);
    }
    red[tid] = m;
    __syncthreads();
#pragma unroll
    for (int s2 = 128; s2 > 0; s2 >>= 1) {
        if (tid < s2) red[tid] = fmaxf(red[tid], red[tid + s2]);
        __syncthreads();
    }
    m = red[0];
    __syncthreads();

    float sum = 0.f;
    for (int c = 0; c < cnt; c++) {
        vals[c] = expf(vals[c] - m);
        sum += vals[c];
    }
    red[tid] = sum;
    __syncthreads();
#pragma unroll
    for (int s2 = 128; s2 > 0; s2 >>= 1) {
        if (tid < s2) red[tid] += red[tid + s2];
        __syncthreads();
    }
    float inv = 1.0f / red[0];

    cnt = 0;
    for (int i = tid; i < len; i += 256) p[i] = vals[cnt++] * inv;
    for (int i = len + tid; i < SEQ; i += 256) p[i] = 0.0f;
}

// attn[bh] = weights_bh (S x S) @ V_b (S x HD), causal K-loop clamp
__global__ __launch_bounds__(256) void k_pv(const float* __restrict__ weights) {
    const int bh = blockIdx.z;
    const int b  = bh / NHEAD;
    const int h  = bh % NHEAD;
    const float* A = weights + (size_t)bh * SEQ * SEQ;            // lda = SEQ
    const float* B = g_v + (size_t)b * SEQ * HD;                  // ldb = HD
    float* C = g_attn + (size_t)b * SEQ * DMODEL + h * HD;        // ldc = DMODEL
    const int kmax = (blockIdx.y + 1) * BM;                       // rows in this tile only attend k < kmax
    gemm_nn_body(A, SEQ, B, HD, C, DMODEL, kmax);
}

// ---------------- launch ----------------
extern "C" void kernel_launch(void* const* d_in, const int* in_sizes, int n_in,
                              void* d_out, int out_size) {
    const float* hidden = (const float*)d_in[0];
    // d_in[1] = attention_mask (deterministic causal) — unused
    const int*   pos    = (const int*)d_in[2];
    const float* Wq     = (const float*)d_in[3];
    const float* Wk     = (const float*)d_in[4];
    const float* Wv     = (const float*)d_in[5];
    const float* Wo     = (const float*)d_in[6];

    float* out      = (float*)d_out;
    float* attn_out = out;                                   // (B, S, H*HD)
    float* weights  = out + (size_t)BATCH * SEQ * DMODEL;    // (B, H, S, S)

    dim3 blk(256);
    const int MB = (BATCH * SEQ) / BM;   // 32

    // 1. projections
    k_proj_q<<<dim3(DMODEL / BN, MB), blk>>>(hidden, Wq);
    k_proj_k<<<dim3(HD / BN, MB), blk>>>(hidden, Wk);
    k_proj_v<<<dim3(HD / BN, MB), blk>>>(hidden, Wv);

    // 2. RoPE in place
    {
        int total = BATCH * SEQ * (NHEAD + 1) * 128;
        k_rope<<<(total + 255) / 256, 256>>>(pos);
    }

    // 3. scores (lower-tri tiles only) -> weights region of d_out
    k_scores<<<dim3(SEQ / BN, SEQ / BM, BH), blk>>>(weights);

    // 4. softmax in place (zeros masked tail)
    k_softmax<<<BH * SEQ, 256>>>(weights);

    // 5. P @ V with causal K clamp
    k_pv<<<dim3(HD / BN, SEQ / BM, BH), blk>>>(weights);

    // 6. output projection
    k_final<<<dim3(DMODEL / BN, MB), blk>>>(Wo, attn_out);
}

// round 3
// speedup vs baseline: 2.6954x; 2.6954x over previous
#include <cuda_runtime.h>
#include <cuda_bf16.h>
#include <cstdint>

#define SEQ    2048
#define DMODEL 2048
#define NHEAD  8
#define HD     256
#define BATCH  2
#define BH     (BATCH*NHEAD)
#define ROWS   (BATCH*SEQ)          // 4096

typedef __nv_bfloat16 bf16;

// ---------------- scratch (device globals; alloc-guard compliant) ----------------
__device__ __align__(256) bf16 s_xhi[(size_t)ROWS*DMODEL],    s_xlo[(size_t)ROWS*DMODEL];
__device__ __align__(256) bf16 s_wqhi[(size_t)DMODEL*DMODEL], s_wqlo[(size_t)DMODEL*DMODEL];
__device__ __align__(256) bf16 s_wkhi[(size_t)HD*DMODEL],     s_wklo[(size_t)HD*DMODEL];
__device__ __align__(256) bf16 s_wvhi[(size_t)HD*DMODEL],     s_wvlo[(size_t)HD*DMODEL];
__device__ __align__(256) bf16 s_wohi[(size_t)DMODEL*DMODEL], s_wolo[(size_t)DMODEL*DMODEL];
__device__ __align__(256) bf16 s_qhi[(size_t)ROWS*DMODEL],    s_qlo[(size_t)ROWS*DMODEL];
__device__ __align__(256) bf16 s_khi[(size_t)ROWS*HD],        s_klo[(size_t)ROWS*HD];
__device__ __align__(256) bf16 s_vthi[(size_t)BATCH*HD*SEQ],  s_vtlo[(size_t)BATCH*HD*SEQ];
__device__ __align__(256) bf16 s_phi[(size_t)BH*SEQ*SEQ],     s_plo[(size_t)BH*SEQ*SEQ];
__device__ __align__(256) bf16 s_ahi[(size_t)ROWS*DMODEL],    s_alo[(size_t)ROWS*DMODEL];
__device__ __align__(16) float g_q[(size_t)ROWS*DMODEL];
__device__ __align__(16) float g_k[(size_t)ROWS*HD];
__device__ __align__(16) float g_v[(size_t)ROWS*HD];
__device__ __align__(16) float g_attn[(size_t)ROWS*DMODEL];

// ---------------- helpers ----------------
__device__ __forceinline__ uint32_t smem_u32(const void* p) {
    uint32_t a;
    asm("{ .reg .u64 t; cvta.to.shared.u64 t, %1; cvt.u32.u64 %0, t; }" : "=r"(a) : "l"(p));
    return a;
}
#define SWZ(o) ((o) ^ (((o) >> 3) & 0x70))

__device__ __forceinline__ void cp16(uint32_t saddr, const void* gaddr) {
    asm volatile("cp.async.cg.shared.global [%0], [%1], 16;" :: "r"(saddr), "l"(gaddr));
}
__device__ __forceinline__ void cp_commit() { asm volatile("cp.async.commit_group;"); }
template<int N> __device__ __forceinline__ void cp_wait() {
    asm volatile("cp.async.wait_group %0;" :: "n"(N));
}
__device__ __forceinline__ void ldsm4(uint32_t* r, uint32_t addr) {
    asm volatile("ldmatrix.sync.aligned.m8n8.x4.shared.b16 {%0,%1,%2,%3}, [%4];"
                 : "=r"(r[0]), "=r"(r[1]), "=r"(r[2]), "=r"(r[3]) : "r"(addr));
}
__device__ __forceinline__ void mma16816(float* c, const uint32_t* a, const uint32_t* b) {
    asm volatile(
        "mma.sync.aligned.m16n8k16.row.col.f32.bf16.bf16.f32 "
        "{%0,%1,%2,%3}, {%4,%5,%6,%7}, {%8,%9}, {%0,%1,%2,%3};"
        : "+f"(c[0]), "+f"(c[1]), "+f"(c[2]), "+f"(c[3])
        : "r"(a[0]), "r"(a[1]), "r"(a[2]), "r"(a[3]), "r"(b[0]), "r"(b[1]));
}

// ---------------- HMMA GEMM: C[M,N] = alpha * A[M,K] @ B[N,K]^T, bf16 hi/lo 3-product ----
#define BM 128
#define BN 128
#define BK 64
#define STG_A_HI 0
#define STG_A_LO 16384
#define STG_B_HI 32768
#define STG_B_LO 49152
#define STG_STRIDE 65536
#define SMEM_BYTES (2*STG_STRIDE)   // 131072

extern __shared__ char dynsmem[];

__device__ __forceinline__ void load_stage(
    uint32_t st, int tid, int k0, int rowBase, int colBase,
    const bf16* ahi, const bf16* alo, int lda,
    const bf16* bhi, const bf16* blo, int ldb)
{
#pragma unroll
    for (int i = 0; i < 4; i++) {
        int idx = tid + i * 256;
        int r = idx >> 3, ch = idx & 7;
        uint32_t so = SWZ((uint32_t)(r * 128 + ch * 16));
        const size_t ao = (size_t)(rowBase + r) * lda + k0 + ch * 8;
        const size_t bo = (size_t)(colBase + r) * ldb + k0 + ch * 8;
        cp16(st + STG_A_HI + so, ahi + ao);
        cp16(st + STG_A_LO + so, alo + ao);
        cp16(st + STG_B_HI + so, bhi + bo);
        cp16(st + STG_B_LO + so, blo + bo);
    }
}

__device__ void hmma_gemm(const bf16* __restrict__ ahi, const bf16* __restrict__ alo, int lda,
                          const bf16* __restrict__ bhi, const bf16* __restrict__ blo, int ldb,
                          float* __restrict__ C, int ldc, int K, float alpha)
{
    const uint32_t sb = smem_u32(dynsmem);
    const int tid = threadIdx.x;
    const int lane = tid & 31, wid = tid >> 5;
    const int warpM = wid >> 2, warpN = wid & 3;     // 2 x 4 warp grid
    const int rowBase = blockIdx.y * BM, colBase = blockIdx.x * BN;

    float acc[4][4][4];
#pragma unroll
    for (int mf = 0; mf < 4; mf++)
#pragma unroll
        for (int nf = 0; nf < 4; nf++)
#pragma unroll
            for (int c = 0; c < 4; c++) acc[mf][nf][c] = 0.f;

    const int KI = K / BK;
    // prologue: stages 0 and 1
    load_stage(sb, tid, 0, rowBase, colBase, ahi, alo, lda, bhi, blo, ldb);
    cp_commit();
    load_stage(sb + STG_STRIDE, tid, BK, rowBase, colBase, ahi, alo, lda, bhi, blo, ldb);
    cp_commit();

    for (int it = 0; it < KI; it++) {
        cp_wait<1>();
        __syncthreads();
        const uint32_t st = sb + (it & 1) * STG_STRIDE;

#pragma unroll
        for (int ks = 0; ks < 4; ks++) {
            uint32_t ah[4][4], al[4][4];
#pragma unroll
            for (int mf = 0; mf < 4; mf++) {
                int row = warpM * 64 + mf * 16 + (lane & 15);
                int kk = ks * 16 + (lane >> 4) * 8;
                uint32_t addr = st + SWZ((uint32_t)(row * 128 + kk * 2));
                ldsm4(ah[mf], addr + STG_A_HI);
                ldsm4(al[mf], addr + STG_A_LO);
            }
            uint32_t bh[4][2], bl[4][2];
#pragma unroll
            for (int nb = 0; nb < 2; nb++) {
                int nrow = warpN * 32 + nb * 16 + (lane & 15);
                int kk = ks * 16 + (lane >> 4) * 8;
                uint32_t addr = st + SWZ((uint32_t)(nrow * 128 + kk * 2));
                uint32_t t[4];
                ldsm4(t, addr + STG_B_HI);
                bh[nb*2][0] = t[0]; bh[nb*2][1] = t[2];
                bh[nb*2+1][0] = t[1]; bh[nb*2+1][1] = t[3];
                ldsm4(t, addr + STG_B_LO);
                bl[nb*2][0] = t[0]; bl[nb*2][1] = t[2];
                bl[nb*2+1][0] = t[1]; bl[nb*2+1][1] = t[3];
            }
#pragma unroll
            for (int mf = 0; mf < 4; mf++)
#pragma unroll
                for (int nf = 0; nf < 4; nf++) {
                    mma16816(acc[mf][nf], ah[mf], bh[nf]);
                    mma16816(acc[mf][nf], ah[mf], bl[nf]);
                    mma16816(acc[mf][nf], al[mf], bh[nf]);
                }
        }
        __syncthreads();
        if (it + 2 < KI)
            load_stage(sb + (it & 1) * STG_STRIDE, tid, (it + 2) * BK,
                       rowBase, colBase, ahi, alo, lda, bhi, blo, ldb);
        cp_commit();
    }
    cp_wait<0>();

    // epilogue: fp32 accum -> gmem
#pragma unroll
    for (int mf = 0; mf < 4; mf++) {
        int row0 = rowBase + warpM * 64 + mf * 16 + (lane >> 2);
#pragma unroll
        for (int nf = 0; nf < 4; nf++) {
            int col = colBase + warpN * 32 + nf * 8 + (lane & 3) * 2;
            float2 v0 = {alpha * acc[mf][nf][0], alpha * acc[mf][nf][1]};
            float2 v1 = {alpha * acc[mf][nf][2], alpha * acc[mf][nf][3]};
            *(float2*)(C + (size_t)row0 * ldc + col) = v0;
            *(float2*)(C + (size_t)(row0 + 8) * ldc + col) = v1;
        }
    }
}

// ---------------- GEMM wrappers ----------------
__global__ __launch_bounds__(256, 1) void k_gemm_plain(
    const bf16* ahi, const bf16* alo, int lda,
    const bf16* bhi, const bf16* blo, int ldb,
    float* C, int ldc, int K, float alpha)
{
    hmma_gemm(ahi, alo, lda, bhi, blo, ldb, C, ldc, K, alpha);
}

__global__ __launch_bounds__(256, 1) void k_gemm_scores(
    const bf16* qhi, const bf16* qlo, const bf16* khi, const bf16* klo, float* W)
{
    if (blockIdx.x > blockIdx.y) return;     // causal: fully-masked tile
    const int bh = blockIdx.z, b = bh / NHEAD, h = bh % NHEAD;
    size_t qa = (size_t)b * SEQ * DMODEL + (size_t)h * HD;
    size_t ka = (size_t)b * SEQ * HD;
    hmma_gemm(qhi + qa, qlo + qa, DMODEL, khi + ka, klo + ka, HD,
              W + (size_t)bh * SEQ * SEQ, SEQ, HD, 0.0625f);
}

__global__ __launch_bounds__(256, 1) void k_gemm_pv(
    const bf16* phi, const bf16* plo, const bf16* vthi, const bf16* vtlo, float* attn)
{
    const int bh = blockIdx.z, b = bh / NHEAD, h = bh % NHEAD;
    size_t pa = (size_t)bh * SEQ * SEQ;
    size_t va = (size_t)b * HD * SEQ;
    int kmax = (blockIdx.y + 1) * BM;        // causal clamp
    hmma_gemm(phi + pa, plo + pa, SEQ, vthi + va, vtlo + va, SEQ,
              attn + (size_t)b * SEQ * DMODEL + (size_t)h * HD, DMODEL, kmax, 1.0f);
}

// ---------------- elementwise fp32 -> bf16 hi/lo split ----------------
__global__ __launch_bounds__(256) void k_cvt(const float4* __restrict__ x,
                                             uint2* __restrict__ hi, uint2* __restrict__ lo, int n4)
{
    int i = blockIdx.x * 256 + threadIdx.x;
    if (i >= n4) return;
    float4 v = x[i];
    bf16 h0 = __float2bfloat16(v.x), h1 = __float2bfloat16(v.y);
    bf16 h2 = __float2bfloat16(v.z), h3 = __float2bfloat16(v.w);
    bf16 g0 = __float2bfloat16(v.x - __bfloat162float(h0));
    bf16 g1 = __float2bfloat16(v.y - __bfloat162float(h1));
    bf16 g2 = __float2bfloat16(v.z - __bfloat162float(h2));
    bf16 g3 = __float2bfloat16(v.w - __bfloat162float(h3));
    uint2 H, L;
    H.x = (uint32_t)__bfloat16_as_ushort(h0) | ((uint32_t)__bfloat16_as_ushort(h1) << 16);
    H.y = (uint32_t)__bfloat16_as_ushort(h2) | ((uint32_t)__bfloat16_as_ushort(h3) << 16);
    L.x = (uint32_t)__bfloat16_as_ushort(g0) | ((uint32_t)__bfloat16_as_ushort(g1) << 16);
    L.y = (uint32_t)__bfloat16_as_ushort(g2) | ((uint32_t)__bfloat16_as_ushort(g3) << 16);
    hi[i] = H;
    lo[i] = L;
}

// ---------------- RoPE (fp32 in) -> bf16 hi/lo planes ----------------
__global__ __launch_bounds__(256) void k_rope_cvt(const int* __restrict__ pos) {
    int idx = blockIdx.x * 256 + threadIdx.x;
    const int total = ROWS * (NHEAD + 1) * 128;
    if (idx >= total) return;
    int j = idx & 127;
    int rest = idx >> 7;
    int slot = rest % (NHEAD + 1);
    int row = rest / (NHEAD + 1);
    float p = (float)pos[row];
    float f = exp2f(-((float)(2 * j) * (1.0f / (float)HD)) * 13.287712379549449f);
    float sv, cv;
    sincosf(p * f, &sv, &cv);
    float x1, x2;
    size_t o;
    if (slot < NHEAD) { o = (size_t)row * DMODEL + slot * HD + j; x1 = g_q[o]; x2 = g_q[o + 128]; }
    else              { o = (size_t)row * HD + j;                 x1 = g_k[o]; x2 = g_k[o + 128]; }
    float y1 = x1 * cv - x2 * sv;
    float y2 = x2 * cv + x1 * sv;
    bf16 h1 = __float2bfloat16(y1), h2 = __float2bfloat16(y2);
    bf16 l1 = __float2bfloat16(y1 - __bfloat162float(h1));
    bf16 l2 = __float2bfloat16(y2 - __bfloat162float(h2));
    if (slot < NHEAD) {
        s_qhi[o] = h1; s_qlo[o] = l1; s_qhi[o + 128] = h2; s_qlo[o + 128] = l2;
    } else {
        s_khi[o] = h1; s_klo[o] = l1; s_khi[o + 128] = h2; s_klo[o + 128] = l2;
    }
}

// ---------------- V transpose + split: g_v[b,k,n] -> vt[b,n,k] ----------------
__global__ void k_vt() {
    __shared__ float t[32][33];
    int b = blockIdx.z;
    int k0 = blockIdx.x * 32, n0 = blockIdx.y * 32;
    int tx = threadIdx.x, ty = threadIdx.y;   // 32 x 8
#pragma unroll
    for (int i = 0; i < 32; i += 8)
        t[ty + i][tx] = g_v[((size_t)(b * SEQ + k0 + ty + i)) * HD + n0 + tx];
    __syncthreads();
#pragma unroll
    for (int i = 0; i < 32; i += 8) {
        float v = t[tx][ty + i];
        bf16 h = __float2bfloat16(v);
        bf16 l = __float2bfloat16(v - __bfloat162float(h));
        size_t o = ((size_t)(b * HD + n0 + ty + i)) * SEQ + k0 + tx;
        s_vthi[o] = h;
        s_vtlo[o] = l;
    }
}

// ---------------- causal softmax (in-place fp32) + bf16 hi/lo plane emit ----------------
__global__ __launch_bounds__(256) void k_softmax(float* __restrict__ w) {
    const int row = blockIdx.x;               // bh*SEQ + q
    const int q = row & (SEQ - 1);
    float* p = w + (size_t)row * SEQ;
    const size_t pb = (size_t)row * SEQ;
    const int len = q + 1;
    const int tid = threadIdx.x;
    __shared__ float red[256];

    float vals[SEQ / 256];
    int cnt = 0;
    float m = -3.4e38f;
    for (int i = tid; i < len; i += 256) {
        float x = p[i];
        vals[cnt++] = x;
        m = fmaxf(m, x);
    }
    red[tid] = m;
    __syncthreads();
#pragma unroll
    for (int s2 = 128; s2 > 0; s2 >>= 1) {
        if (tid < s2) red[tid] = fmaxf(red[tid], red[tid + s2]);
        __syncthreads();
    }
    m = red[0];
    __syncthreads();

    float sum = 0.f;
    for (int c = 0; c < cnt; c++) {
        vals[c] = expf(vals[c] - m);
        sum += vals[c];
    }
    red[tid] = sum;
    __syncthreads();
#pragma unroll
    for (int s2 = 128; s2 > 0; s2 >>= 1) {
        if (tid < s2) red[tid] += red[tid + s2];
        __syncthreads();
    }
    float inv = 1.0f / red[0];

    cnt = 0;
    for (int i = tid; i < len; i += 256) {
        float v = vals[cnt++] * inv;
        p[i] = v;
        bf16 h = __float2bfloat16(v);
        s_phi[pb + i] = h;
        s_plo[pb + i] = __float2bfloat16(v - __bfloat162float(h));
    }
    const bf16 z = __float2bfloat16(0.0f);
    for (int i = len + tid; i < SEQ; i += 256) {
        p[i] = 0.0f;
        s_phi[pb + i] = z;
        s_plo[pb + i] = z;
    }
}

// ---------------- launch ----------------
static void* sym(const void* s) { void* p = nullptr; cudaGetSymbolAddress(&p, s); return p; }

extern "C" void kernel_launch(void* const* d_in, const int* in_sizes, int n_in,
                              void* d_out, int out_size) {
    const float* hidden = (const float*)d_in[0];
    const int*   pos    = (const int*)d_in[2];
    const float* Wq     = (const float*)d_in[3];
    const float* Wk     = (const float*)d_in[4];
    const float* Wv     = (const float*)d_in[5];
    const float* Wo     = (const float*)d_in[6];

    float* out      = (float*)d_out;
    float* weights  = out + (size_t)ROWS * DMODEL;   // (B, H, S, S)

    cudaFuncSetAttribute(k_gemm_plain,  cudaFuncAttributeMaxDynamicSharedMemorySize, SMEM_BYTES);
    cudaFuncSetAttribute(k_gemm_scores, cudaFuncAttributeMaxDynamicSharedMemorySize, SMEM_BYTES);
    cudaFuncSetAttribute(k_gemm_pv,     cudaFuncAttributeMaxDynamicSharedMemorySize, SMEM_BYTES);

    bf16 *xhi = (bf16*)sym(s_xhi),  *xlo = (bf16*)sym(s_xlo);
    bf16 *wqh = (bf16*)sym(s_wqhi), *wql = (bf16*)sym(s_wqlo);
    bf16 *wkh = (bf16*)sym(s_wkhi), *wkl = (bf16*)sym(s_wklo);
    bf16 *wvh = (bf16*)sym(s_wvhi), *wvl = (bf16*)sym(s_wvlo);
    bf16 *woh = (bf16*)sym(s_wohi), *wol = (bf16*)sym(s_wolo);
    bf16 *qhi = (bf16*)sym(s_qhi),  *qlo = (bf16*)sym(s_qlo);
    bf16 *khi = (bf16*)sym(s_khi),  *klo = (bf16*)sym(s_klo);
    bf16 *vth = (bf16*)sym(s_vthi), *vtl = (bf16*)sym(s_vtlo);
    bf16 *phi = (bf16*)sym(s_phi),  *plo = (bf16*)sym(s_plo);
    bf16 *ahi = (bf16*)sym(s_ahi),  *alo = (bf16*)sym(s_alo);
    float *gq = (float*)sym(g_q), *gk = (float*)sym(g_k);
    float *gv = (float*)sym(g_v), *ga = (float*)sym(g_attn);

    // 1. split inputs/weights into bf16 hi/lo planes
    {
        int n4 = ROWS * DMODEL / 4;
        k_cvt<<<(n4 + 255) / 256, 256>>>((const float4*)hidden, (uint2*)xhi, (uint2*)xlo, n4);
        n4 = DMODEL * DMODEL / 4;
        k_cvt<<<(n4 + 255) / 256, 256>>>((const float4*)Wq, (uint2*)wqh, (uint2*)wql, n4);
        k_cvt<<<(n4 + 255) / 256, 256>>>((const float4*)Wo, (uint2*)woh, (uint2*)wol, n4);
        n4 = HD * DMODEL / 4;
        k_cvt<<<(n4 + 255) / 256, 256>>>((const float4*)Wk, (uint2*)wkh, (uint2*)wkl, n4);
        k_cvt<<<(n4 + 255) / 256, 256>>>((const float4*)Wv, (uint2*)wvh, (uint2*)wvl, n4);
    }

    // 2. projections (HMMA)
    k_gemm_plain<<<dim3(DMODEL / BN, ROWS / BM), 256, SMEM_BYTES>>>(xhi, xlo, DMODEL, wqh, wql, DMODEL, gq, DMODEL, DMODEL, 1.0f);
    k_gemm_plain<<<dim3(HD / BN, ROWS / BM),     256, SMEM_BYTES>>>(xhi, xlo, DMODEL, wkh, wkl, DMODEL, gk, HD, DMODEL, 1.0f);
    k_gemm_plain<<<dim3(HD / BN, ROWS / BM),     256, SMEM_BYTES>>>(xhi, xlo, DMODEL, wvh, wvl, DMODEL, gv, HD, DMODEL, 1.0f);

    // 3. RoPE -> bf16 planes ; V transpose -> bf16 planes
    {
        int total = ROWS * (NHEAD + 1) * 128;
        k_rope_cvt<<<(total + 255) / 256, 256>>>(pos);
    }
    k_vt<<<dim3(SEQ / 32, HD / 32, BATCH), dim3(32, 8)>>>();

    // 4. scores (causal tile skip) -> weights fp32 region of d_out
    k_gemm_scores<<<dim3(SEQ / BN, SEQ / BM, BH), 256, SMEM_BYTES>>>(qhi, qlo, khi, klo, weights);

    // 5. softmax in place + emit P bf16 planes
    k_softmax<<<BH * SEQ, 256>>>(weights);

    // 6. P @ V  (causal K clamp)
    k_gemm_pv<<<dim3(HD / BN, SEQ / BM, BH), 256, SMEM_BYTES>>>(phi, plo, vth, vtl, ga);

    // 7. split attn, output projection
    {
        int n4 = ROWS * DMODEL / 4;
        k_cvt<<<(n4 + 255) / 256, 256>>>((const float4*)ga, (uint2*)ahi, (uint2*)alo, n4);
    }
    k_gemm_plain<<<dim3(DMODEL / BN, ROWS / BM), 256, SMEM_BYTES>>>(ahi, alo, DMODEL, woh, wol, DMODEL, out, DMODEL, DMODEL, 1.0f);
}